// round 1
// baseline (speedup 1.0000x reference)
#include <cuda_runtime.h>
#include <cstdint>

#define USER_NUM 50000
#define ITEM_NUM 50000
#define NTOT     100000
#define VT_DIM   512
#define CAT_DIM  32
#define HID      128
#define OUTD     64

// ---------------- static scratch (no allocs allowed) ----------------
__device__ float g_x0[(size_t)NTOT * HID];    // [user; item_feat]
__device__ float g_h1[(size_t)NTOT * HID];    // x0 @ w1_l.T
__device__ float g_s1[(size_t)NTOT * HID];    // edge-aggregated sums (conv1)
__device__ float g_x1[(size_t)NTOT * HID];    // leaky(conv1)
__device__ float g_h2[(size_t)NTOT * OUTD];   // x1 @ w2_l.T
__device__ float g_s2[(size_t)NTOT * OUTD];   // edge-aggregated sums (conv2)
__device__ float g_cat[(size_t)ITEM_NUM * CAT_DIM];
__device__ float g_deg[NTOT];

// ---------------- helpers ----------------
__device__ __forceinline__ void red_add_v4(float* p, float4 v) {
    asm volatile("red.global.add.v4.f32 [%0], {%1, %2, %3, %4};"
                 :: "l"(p), "f"(v.x), "f"(v.y), "f"(v.z), "f"(v.w) : "memory");
}

// ---------------- zero scratch ----------------
__global__ void zero_fill_kernel() {
    size_t n1 = (size_t)NTOT * HID / 4;   // g_s1 float4s
    size_t n2 = (size_t)NTOT * OUTD / 4;  // g_s2 float4s
    size_t stride = (size_t)gridDim.x * blockDim.x;
    size_t gid = (size_t)blockIdx.x * blockDim.x + threadIdx.x;
    float4 z = make_float4(0.f, 0.f, 0.f, 0.f);
    for (size_t i = gid; i < n1; i += stride) ((float4*)g_s1)[i] = z;
    for (size_t i = gid; i < n2; i += stride) ((float4*)g_s2)[i] = z;
    for (size_t i = gid; i < NTOT; i += stride) g_deg[i] = 0.f;
}

// ---------------- copy user rows into x0 ----------------
__global__ void copy_user_kernel(const float* __restrict__ user) {
    size_t n = (size_t)USER_NUM * HID / 4;
    size_t gid = (size_t)blockIdx.x * blockDim.x + threadIdx.x;
    if (gid < n) ((float4*)g_x0)[gid] = ((const float4*)user)[gid];
}

// ---------------- embedding bag (mean of ~5 rows of 32) ----------------
__global__ void catbag_kernel(const float* __restrict__ table,
                              const int* __restrict__ idx,
                              const int* __restrict__ offs,
                              int tot_idx) {
    int gid = blockIdx.x * blockDim.x + threadIdx.x;     // ITEM_NUM * 8 lanes
    if (gid >= ITEM_NUM * 8) return;
    int bag  = gid >> 3;
    int comp = (gid & 7) * 4;
    int beg = offs[bag];
    int end = (bag + 1 < ITEM_NUM) ? offs[bag + 1] : tot_idx;
    float4 s = make_float4(0.f, 0.f, 0.f, 0.f);
    for (int j = beg; j < end; j++) {
        int ix = __ldg(&idx[j]);
        float4 t = *(const float4*)(table + (size_t)ix * CAT_DIM + comp);
        s.x += t.x; s.y += t.y; s.z += t.z; s.w += t.w;
    }
    float inv = 1.0f / (float)max(end - beg, 1);
    s.x *= inv; s.y *= inv; s.z *= inv; s.w *= inv;
    *(float4*)(g_cat + (size_t)bag * CAT_DIM + comp) = s;
}

// ---------------- degree ----------------
__global__ void deg_kernel(const int* __restrict__ dst, int E) {
    int stride = gridDim.x * blockDim.x;
    for (int e = blockIdx.x * blockDim.x + threadIdx.x; e < E; e += stride)
        atomicAdd(&g_deg[__ldg(&dst[e])], 1.0f);
}

// ---------------- edge scatter: s[dst] += h[src], NC floats/row ----------------
template <int NC>
__global__ void scatter_kernel(const float* __restrict__ h,
                               const int* __restrict__ src,
                               const int* __restrict__ dst,
                               float* __restrict__ s, int E) {
    constexpr int LPE = NC / 4;                      // lanes per edge (32 or 16)
    int lane = threadIdx.x & (LPE - 1);
    int eg = (blockIdx.x * blockDim.x + threadIdx.x) / LPE;
    int estride = (gridDim.x * blockDim.x) / LPE;
    for (int e = eg; e < E; e += estride) {
        int si = __ldg(&src[e]);
        int di = __ldg(&dst[e]);
        float4 v = *(const float4*)(h + (size_t)si * NC + lane * 4);
        red_add_v4(s + (size_t)di * NC + lane * 4, v);
    }
}

// ---------------- tiled SIMT GEMM:  C[M,NC] = A[M,K] @ W[NC,K]^T (+epilogue) --
// EPI: 0 = plain, 1 = leaky(C + b + s/deg), 2 = C + b + s/deg
template <int NC, int EPI, bool FUSED>
__global__ __launch_bounds__(256)
void gemm_kernel(const float* __restrict__ A, int K,
                 const float* __restrict__ A2,          // cat part when FUSED
                 const float* __restrict__ W,
                 const float* __restrict__ bias,
                 const float* __restrict__ sagg,
                 const float* __restrict__ degp,
                 float* __restrict__ C, int M) {
    constexpr int BM = 64, BK = 32;
    constexpr int CPT = NC / 16;                       // cols per thread (8 or 4)
    __shared__ float As[BM][BK];                       // row-major (k contiguous)
    __shared__ float Ws[BK][NC + 4];                   // k-major (c contiguous)

    int tid = threadIdx.x;
    int tx = tid & 15, ty = tid >> 4;
    int row0 = blockIdx.x * BM;
    int r0 = ty * 4;
    int c0 = tx * CPT;

    float acc[4][CPT];
#pragma unroll
    for (int i = 0; i < 4; i++)
#pragma unroll
        for (int j = 0; j < CPT; j++) acc[i][j] = 0.f;

    int nchunks = K / BK;
    for (int ch = 0; ch < nchunks; ch++) {
        int kk = ch * BK;
        // --- load A tile: 64x32, 2 float4 per thread ---
        {
            int ar = tid >> 2;
            int kc = (tid & 3) * 8;
            int grow = row0 + ar;
            float4 v0 = make_float4(0, 0, 0, 0), v1 = v0;
            if (grow < M) {
                const float* base;
                int koff;
                if (!FUSED) { base = A; koff = kk + kc; base += (size_t)grow * K; }
                else if (kk < VT_DIM) { base = A + (size_t)grow * VT_DIM; koff = kk + kc; }
                else { base = A2 + (size_t)grow * CAT_DIM; koff = kk - VT_DIM + kc; }
                const float4* p = (const float4*)(base + koff);
                v0 = p[0]; v1 = p[1];
            }
            *(float4*)&As[ar][kc] = v0;
            *(float4*)&As[ar][kc + 4] = v1;
        }
        // --- load W tile: NC x 32, transposed into Ws[k][c] ---
        {
            constexpr int TOT = NC * 8;                // float4 count
#pragma unroll
            for (int j = 0; j < TOT / 256; j++) {
                int idx = j * 256 + tid;
                int c = idx >> 3;
                int kq = idx & 7;
                float4 w = *(const float4*)(W + (size_t)c * K + kk + kq * 4);
                Ws[kq * 4 + 0][c] = w.x;
                Ws[kq * 4 + 1][c] = w.y;
                Ws[kq * 4 + 2][c] = w.z;
                Ws[kq * 4 + 3][c] = w.w;
            }
        }
        __syncthreads();
        // --- compute ---
#pragma unroll
        for (int k4 = 0; k4 < BK; k4 += 4) {
            float a[4][4];
#pragma unroll
            for (int i = 0; i < 4; i++) {
                float4 t = *(const float4*)&As[r0 + i][k4];
                a[i][0] = t.x; a[i][1] = t.y; a[i][2] = t.z; a[i][3] = t.w;
            }
#pragma unroll
            for (int kq = 0; kq < 4; kq++) {
                float w[CPT];
#pragma unroll
                for (int q = 0; q < CPT / 4; q++) {
                    float4 t = *(const float4*)&Ws[k4 + kq][c0 + q * 4];
                    w[q * 4 + 0] = t.x; w[q * 4 + 1] = t.y;
                    w[q * 4 + 2] = t.z; w[q * 4 + 3] = t.w;
                }
#pragma unroll
                for (int i = 0; i < 4; i++)
#pragma unroll
                    for (int j = 0; j < CPT; j++)
                        acc[i][j] = fmaf(a[i][kq], w[j], acc[i][j]);
            }
        }
        __syncthreads();
    }
    // --- epilogue ---
#pragma unroll
    for (int i = 0; i < 4; i++) {
        int gr = row0 + r0 + i;
        if (gr >= M) continue;
        float dinv = 0.f;
        if (EPI != 0) dinv = 1.0f / fmaxf(degp[gr], 1.0f);
#pragma unroll
        for (int q = 0; q < CPT / 4; q++) {
            int gc = c0 + q * 4;
            float4 v;
            v.x = acc[i][q * 4 + 0]; v.y = acc[i][q * 4 + 1];
            v.z = acc[i][q * 4 + 2]; v.w = acc[i][q * 4 + 3];
            if (EPI != 0) {
                float4 sv = *(const float4*)(sagg + (size_t)gr * NC + gc);
                v.x += bias[gc + 0] + sv.x * dinv;
                v.y += bias[gc + 1] + sv.y * dinv;
                v.z += bias[gc + 2] + sv.z * dinv;
                v.w += bias[gc + 3] + sv.w * dinv;
                if (EPI == 1) {
                    v.x = v.x > 0.f ? v.x : 0.01f * v.x;
                    v.y = v.y > 0.f ? v.y : 0.01f * v.y;
                    v.z = v.z > 0.f ? v.z : 0.01f * v.z;
                    v.w = v.w > 0.f ? v.w : 0.01f * v.w;
                }
            }
            *(float4*)(C + (size_t)gr * NC + gc) = v;
        }
    }
}

// ---------------- launch ----------------
extern "C" void kernel_launch(void* const* d_in, const int* in_sizes, int n_in,
                              void* d_out, int out_size) {
    const float* vt      = (const float*)d_in[0];
    const int*   cat_idx = (const int*)d_in[1];
    const int*   cat_off = (const int*)d_in[2];
    const int*   edge    = (const int*)d_in[3];
    const float* cat_tab = (const float*)d_in[4];
    const float* fuse_w  = (const float*)d_in[5];
    const float* user    = (const float*)d_in[6];
    const float* w1_l    = (const float*)d_in[7];
    const float* b1      = (const float*)d_in[8];
    const float* w1_r    = (const float*)d_in[9];
    const float* w2_l    = (const float*)d_in[10];
    const float* b2      = (const float*)d_in[11];
    const float* w2_r    = (const float*)d_in[12];

    int E = in_sizes[3] / 2;
    const int* src = edge;
    const int* dst = edge + E;
    int tot_idx = in_sizes[1];

    float *x0p, *h1p, *s1p, *x1p, *h2p, *s2p, *catp, *degp;
    cudaGetSymbolAddress((void**)&x0p, g_x0);
    cudaGetSymbolAddress((void**)&h1p, g_h1);
    cudaGetSymbolAddress((void**)&s1p, g_s1);
    cudaGetSymbolAddress((void**)&x1p, g_x1);
    cudaGetSymbolAddress((void**)&h2p, g_h2);
    cudaGetSymbolAddress((void**)&s2p, g_s2);
    cudaGetSymbolAddress((void**)&catp, g_cat);
    cudaGetSymbolAddress((void**)&degp, g_deg);

    const int grid_item = (ITEM_NUM + 63) / 64;   // 782
    const int grid_all  = (NTOT + 63) / 64;       // 1563

    // 1. zero scratch
    zero_fill_kernel<<<2048, 256>>>();
    // 2. x0[0:USER] = user
    copy_user_kernel<<<(USER_NUM * HID / 4 + 255) / 256, 256>>>(user);
    // 3. cat embedding bag
    catbag_kernel<<<(ITEM_NUM * 8 + 255) / 256, 256>>>(cat_tab, cat_idx, cat_off, tot_idx);
    // 4. item_feat = [vt | cat] @ fuse_w.T  -> x0[USER:]
    gemm_kernel<128, 0, true><<<grid_item, 256>>>(
        vt, VT_DIM + CAT_DIM, catp, fuse_w, nullptr, nullptr, nullptr,
        x0p + (size_t)USER_NUM * HID, ITEM_NUM);
    // 5. degree
    deg_kernel<<<2048, 256>>>(dst, E);
    // 6. h1 = x0 @ w1_l.T
    gemm_kernel<128, 0, false><<<grid_all, 256>>>(
        x0p, HID, nullptr, w1_l, nullptr, nullptr, nullptr, h1p, NTOT);
    // 7. s1[dst] += h1[src]
    scatter_kernel<128><<<2048, 256>>>(h1p, src, dst, s1p, E);
    // 8. x1 = leaky(s1/deg + b1 + x0 @ w1_r.T)
    gemm_kernel<128, 1, false><<<grid_all, 256>>>(
        x0p, HID, nullptr, w1_r, b1, s1p, degp, x1p, NTOT);
    // 9. h2 = x1 @ w2_l.T
    gemm_kernel<64, 0, false><<<grid_all, 256>>>(
        x1p, HID, nullptr, w2_l, nullptr, nullptr, nullptr, h2p, NTOT);
    // 10. s2[dst] += h2[src]
    scatter_kernel<64><<<2048, 256>>>(h2p, src, dst, s2p, E);
    // 11. out = s2/deg + b2 + x1 @ w2_r.T
    gemm_kernel<64, 2, false><<<grid_all, 256>>>(
        x1p, HID, nullptr, w2_r, b2, s2p, degp, (float*)d_out, NTOT);
}